// round 1
// baseline (speedup 1.0000x reference)
#include <cuda_runtime.h>

#define NTOK 32768
#define DIM  512
#define KCB  8192
#define BM   64
#define BN   128
#define KT   16

// output layout (flat float32 concat, reference return order)
#define O_LOSS  ((size_t)0)
#define O_ZQ    ((size_t)1)
#define O_CODES ((size_t)(1 + (size_t)NTOK*DIM))          // 16777217
#define O_NW    ((size_t)(O_CODES + NTOK))                 // 16809985
#define O_NCS   ((size_t)(O_NW + (size_t)KCB*DIM))         // 21004289
#define O_NEW   ((size_t)(O_NCS + KCB))                    // 21012481

__device__ int   g_codes[NTOK];
__device__ float g_wn[KCB];     // 0.5 * ||w_k||^2
__device__ float g_loss;
__device__ float g_nsum;

// ---------------------------------------------------------------------------
// init: new_ema_w = 0.99*ema_w, new_cs = 0.99*ema_cs, zero scalars
// ---------------------------------------------------------------------------
__global__ void init_kernel(const float* __restrict__ ema_w,
                            const float* __restrict__ ema_cs,
                            float* __restrict__ out) {
    int idx = blockIdx.x * blockDim.x + threadIdx.x;
    if (idx < KCB * DIM) out[O_NEW + idx] = 0.99f * ema_w[idx];
    if (idx < KCB)       out[O_NCS + idx] = 0.99f * ema_cs[idx];
    if (idx == 0) { g_loss = 0.0f; g_nsum = 0.0f; }
}

// ---------------------------------------------------------------------------
// wn: 0.5 * row sumsq of weight, one warp per row
// ---------------------------------------------------------------------------
__global__ void wn_kernel(const float* __restrict__ weight) {
    int gw   = (blockIdx.x * blockDim.x + threadIdx.x) >> 5;
    int lane = threadIdx.x & 31;
    if (gw >= KCB) return;
    const float4* row = (const float4*)(weight + (size_t)gw * DIM);
    float s = 0.0f;
#pragma unroll
    for (int p = 0; p < 4; p++) {
        float4 v = row[p * 32 + lane];
        s += v.x * v.x + v.y * v.y + v.z * v.z + v.w * v.w;
    }
#pragma unroll
    for (int o = 16; o > 0; o >>= 1) s += __shfl_xor_sync(0xffffffffu, s, o);
    if (lane == 0) g_wn[gw] = 0.5f * s;
}

// ---------------------------------------------------------------------------
// fused GEMM + argmax:  codes[n] = argmax_k ( z_n . w_k - 0.5||w_k||^2 )
// block: 64 tokens, loops all 8192 codes in BN=128 chunks, K=512 full depth.
// smem: zs[512][64] (transposed z tile) | ws[2][16][128] (dbl-buffer) | wns[8192]
// ---------------------------------------------------------------------------
__global__ void __launch_bounds__(256, 1)
argmax_kernel(const float* __restrict__ z,
              const float* __restrict__ weight,
              float* __restrict__ out) {
    extern __shared__ float sm[];
    float* zs  = sm;                        // 32768 floats
    float* ws  = sm + BM * DIM;             // 4096 floats (2 * 16 * 128)
    float* wns = ws + 2 * KT * BN;          // 8192 floats

    const int tid = threadIdx.x;
    const int t0  = blockIdx.x * BM;

    // load z tile transposed: zs[d][token]
    const float4* z4 = (const float4*)z;
    for (int f = tid; f < BM * (DIM / 4); f += 256) {
        int token = f & (BM - 1);
        int d4    = f >> 6;                 // f / BM
        float4 v  = z4[(size_t)(t0 + token) * (DIM / 4) + d4];
        zs[(d4 * 4 + 0) * BM + token] = v.x;
        zs[(d4 * 4 + 1) * BM + token] = v.y;
        zs[(d4 * 4 + 2) * BM + token] = v.z;
        zs[(d4 * 4 + 3) * BM + token] = v.w;
    }
    for (int i = tid; i < KCB; i += 256) wns[i] = g_wn[i];
    __syncthreads();

    const int tx  = tid & 15;
    const int ty  = tid >> 4;
    const int ty4 = ty * 4;
    const int tx8 = tx * 8;

    // per-thread weight staging map (2 float4 per chunk)
    const int j1 = tid >> 2,         kk41 = tid & 3;
    const int j2 = (tid + 256) >> 2, kk42 = (tid + 256) & 3;
    const float4* W4 = (const float4*)weight;

    float best[4];
    int   bidx[4];
#pragma unroll
    for (int i = 0; i < 4; i++) { best[i] = -3.4e38f; bidx[i] = 0; }

    for (int c = 0; c < KCB / BN; c++) {
        const int cb = c * BN;
        float acc[4][8];
#pragma unroll
        for (int i = 0; i < 4; i++)
#pragma unroll
            for (int j = 0; j < 8; j++) acc[i][j] = 0.0f;

        // stage k-chunk 0 into buffer 0
        {
            float4 v1 = W4[(size_t)(cb + j1) * (DIM / 4) + kk41];
            float4 v2 = W4[(size_t)(cb + j2) * (DIM / 4) + kk42];
            float* p1 = ws + (kk41 * 4) * BN + j1;
            p1[0] = v1.x; p1[BN] = v1.y; p1[2 * BN] = v1.z; p1[3 * BN] = v1.w;
            float* p2 = ws + (kk42 * 4) * BN + j2;
            p2[0] = v2.x; p2[BN] = v2.y; p2[2 * BN] = v2.z; p2[3 * BN] = v2.w;
        }
        __syncthreads();

        for (int kt = 0; kt < DIM / KT; kt++) {
            const int cur = kt & 1;
            float4 p1v, p2v;
            const bool pre = (kt + 1) < (DIM / KT);
            if (pre) {
                p1v = W4[(size_t)(cb + j1) * (DIM / 4) + (kt + 1) * (KT / 4) + kk41];
                p2v = W4[(size_t)(cb + j2) * (DIM / 4) + (kt + 1) * (KT / 4) + kk42];
            }
            const float* wbuf = ws + cur * (KT * BN);
            const int kb = kt * KT;
#pragma unroll
            for (int kk = 0; kk < KT; kk++) {
                const float4 zv = *(const float4*)(zs + (kb + kk) * BM + ty4);
                const float4 wa = *(const float4*)(wbuf + kk * BN + tx8);
                const float4 wc = *(const float4*)(wbuf + kk * BN + tx8 + 4);
                float zr[4] = {zv.x, zv.y, zv.z, zv.w};
                float wr[8] = {wa.x, wa.y, wa.z, wa.w, wc.x, wc.y, wc.z, wc.w};
#pragma unroll
                for (int i = 0; i < 4; i++)
#pragma unroll
                    for (int j = 0; j < 8; j++) acc[i][j] += zr[i] * wr[j];
            }
            if (pre) {
                float* q = ws + (cur ^ 1) * (KT * BN);
                float* p1 = q + (kk41 * 4) * BN + j1;
                p1[0] = p1v.x; p1[BN] = p1v.y; p1[2 * BN] = p1v.z; p1[3 * BN] = p1v.w;
                float* p2 = q + (kk42 * 4) * BN + j2;
                p2[0] = p2v.x; p2[BN] = p2v.y; p2[2 * BN] = p2v.z; p2[3 * BN] = p2v.w;
            }
            __syncthreads();
        }

        // running argmax update (metric = dot - 0.5||w||^2); strict > keeps
        // lowest index on ties, matching argmin-first semantics
#pragma unroll
        for (int i = 0; i < 4; i++)
#pragma unroll
            for (int j = 0; j < 8; j++) {
                float m = acc[i][j] - wns[cb + tx8 + j];
                if (m > best[i]) { best[i] = m; bidx[i] = cb + tx8 + j; }
            }
    }

    // cross-thread reduction: 16 tx candidates per token (ascending tx keeps ties low-index)
    float* redv = ws;                         // 64*16 floats
    int*   redi = (int*)(ws + BM * 16);
#pragma unroll
    for (int i = 0; i < 4; i++) {
        int t = ty4 + i;
        redv[t * 16 + tx] = best[i];
        redi[t * 16 + tx] = bidx[i];
    }
    __syncthreads();
    if (tid < BM) {
        float bv = redv[tid * 16];
        int   bi = redi[tid * 16];
#pragma unroll
        for (int x = 1; x < 16; x++) {
            float v = redv[tid * 16 + x];
            if (v > bv) { bv = v; bi = redi[tid * 16 + x]; }
        }
        g_codes[t0 + tid] = bi;
        out[O_CODES + t0 + tid] = (float)bi;
    }
}

// ---------------------------------------------------------------------------
// scatter: new_cs += 0.01 per token; new_ema_w[code] += 0.01 * z[token]
// ---------------------------------------------------------------------------
__global__ void scatter_kernel(const float* __restrict__ z, float* __restrict__ out) {
    int token = blockIdx.x;
    int tid   = threadIdx.x;
    int code  = g_codes[token];
    if (tid == 0) atomicAdd(out + O_NCS + code, 0.01f);
    const float* zr  = z + (size_t)token * DIM;
    float*       dst = out + O_NEW + (size_t)code * DIM;
#pragma unroll
    for (int i = 0; i < 4; i++) {
        int d = i * 128 + tid;
        atomicAdd(dst + d, 0.01f * zr[d]);
    }
}

// ---------------------------------------------------------------------------
// nsum = sum(new_cs)
// ---------------------------------------------------------------------------
__global__ void nsum_kernel(const float* __restrict__ out) {
    __shared__ float red[1024];
    int tid = threadIdx.x;
    float s = 0.0f;
    for (int i = tid; i < KCB; i += 1024) s += out[O_NCS + i];
    red[tid] = s;
    __syncthreads();
    for (int o = 512; o > 0; o >>= 1) {
        if (tid < o) red[tid] += red[tid + o];
        __syncthreads();
    }
    if (tid == 0) g_nsum = red[0];
}

// ---------------------------------------------------------------------------
// new_weight = new_ema_w / cluster_size
// ---------------------------------------------------------------------------
__global__ void weight_kernel(float* __restrict__ out) {
    int idx = blockIdx.x * blockDim.x + threadIdx.x;
    if (idx >= KCB * DIM) return;
    int k = idx >> 9;
    float n  = g_nsum;
    float cs = (out[O_NCS + k] + 1e-5f) / (n + KCB * 1e-5f) * n;
    out[O_NW + idx] = out[O_NEW + idx] / cs;
}

// ---------------------------------------------------------------------------
// gather z_q, straight-through output, loss partial sums
// ---------------------------------------------------------------------------
__global__ void gather_kernel(const float* __restrict__ z, float* __restrict__ out) {
    __shared__ float red[128];
    int token = blockIdx.x;
    int tid   = threadIdx.x;
    int code  = g_codes[token];
    const float* wr = out + O_NW + (size_t)code * DIM;
    const float* zr = z + (size_t)token * DIM;
    float*       oq = out + O_ZQ + (size_t)token * DIM;
    float ls = 0.0f;
#pragma unroll
    for (int i = 0; i < 4; i++) {
        int d   = i * 128 + tid;
        float w = wr[d];
        float v = zr[d];
        float t = w - v;                  // z_q - z
        oq[d]   = v + t;                  // z + (z_q - z), matches reference fp order
        ls += t * t;
    }
    red[tid] = ls;
    __syncthreads();
    for (int o = 64; o > 0; o >>= 1) {
        if (tid < o) red[tid] += red[tid + o];
        __syncthreads();
    }
    if (tid == 0) atomicAdd(&g_loss, red[0]);
}

__global__ void finalize_kernel(float* __restrict__ out) {
    out[O_LOSS] = 0.25f * g_loss / (float)(NTOK * DIM);
}

// ---------------------------------------------------------------------------
extern "C" void kernel_launch(void* const* d_in, const int* in_sizes, int n_in,
                              void* d_out, int out_size) {
    const float* z      = (const float*)d_in[0];
    const float* weight = (const float*)d_in[1];
    const float* ema_cs = (const float*)d_in[2];
    const float* ema_w  = (const float*)d_in[3];
    float* out = (float*)d_out;

    const int smem_bytes = (BM * DIM + 2 * KT * BN + KCB) * 4;   // 180224
    cudaFuncSetAttribute(argmax_kernel, cudaFuncAttributeMaxDynamicSharedMemorySize,
                         smem_bytes);

    init_kernel<<<(KCB * DIM + 255) / 256, 256>>>(ema_w, ema_cs, out);
    wn_kernel<<<KCB / 8, 256>>>(weight);
    argmax_kernel<<<NTOK / BM, 256, smem_bytes>>>(z, weight, out);
    scatter_kernel<<<NTOK, 128>>>(z, out);
    nsum_kernel<<<1, 1024>>>(out);
    weight_kernel<<<(KCB * DIM + 255) / 256, 256>>>(out);
    gather_kernel<<<NTOK, 128>>>(z, out);
    finalize_kernel<<<1, 1>>>(out);
}

// round 3
// speedup vs baseline: 2.9714x; 2.9714x over previous
#include <cuda_runtime.h>
#include <cuda_bf16.h>
#include <cstdint>

#define NTOK 32768
#define DIM  512
#define KCB  8192

#define NPROD  6
#define KEXT   (NPROD * DIM)      // 3072
#define BM     128
#define BN     128
#define BK     64
#define NCHUNK (KEXT / BK)        // 48
#define STAGES 3
#define TILE_BYTES (BM * BK * 2)  // 16384

// output layout (flat float32 concat, reference return order)
#define O_LOSS  ((size_t)0)
#define O_ZQ    ((size_t)1)
#define O_CODES ((size_t)(1 + (size_t)NTOK*DIM))
#define O_NW    ((size_t)(O_CODES + NTOK))
#define O_NCS   ((size_t)(O_NW + (size_t)KCB*DIM))
#define O_NEW   ((size_t)(O_NCS + KCB))

// ---- device scratch (static: no allocation allowed) ----
__device__ __align__(16) __nv_bfloat16 g_A[(size_t)NTOK * KEXT];  // 192 MB
__device__ __align__(16) __nv_bfloat16 g_B[(size_t)KCB  * KEXT];  // 48 MB
__device__ unsigned long long g_best[NTOK];
__device__ int   g_codes[NTOK];
__device__ float g_wn[KCB];
__device__ float g_loss;
__device__ float g_nsum;

// ---------------------------------------------------------------------------
// PTX helpers (sm_80-era only: supported at base sm_103 PTX target)
// ---------------------------------------------------------------------------
__device__ __forceinline__ uint32_t smem_u32(const void* p) {
    uint32_t a;
    asm("{ .reg .u64 t; cvta.to.shared.u64 t, %1; cvt.u32.u64 %0, t; }" : "=r"(a) : "l"(p));
    return a;
}
__device__ __forceinline__ void cp16(uint32_t s, const void* g) {
    asm volatile("cp.async.cg.shared.global [%0], [%1], 16;" :: "r"(s), "l"(g));
}
#define CP_COMMIT() asm volatile("cp.async.commit_group;" ::: "memory")
#define CP_WAIT(n)  asm volatile("cp.async.wait_group %0;" :: "n"(n) : "memory")

__device__ __forceinline__ void ldsm4(uint32_t& r0, uint32_t& r1, uint32_t& r2, uint32_t& r3,
                                      uint32_t addr) {
    asm volatile("ldmatrix.sync.aligned.m8n8.x4.shared.b16 {%0,%1,%2,%3}, [%4];"
                 : "=r"(r0), "=r"(r1), "=r"(r2), "=r"(r3) : "r"(addr));
}
__device__ __forceinline__ void mma16816(float* d, uint32_t a0, uint32_t a1, uint32_t a2,
                                         uint32_t a3, uint32_t b0, uint32_t b1) {
    asm volatile(
        "mma.sync.aligned.m16n8k16.row.col.f32.bf16.bf16.f32 "
        "{%0,%1,%2,%3},{%4,%5,%6,%7},{%8,%9},{%0,%1,%2,%3};"
        : "+f"(d[0]), "+f"(d[1]), "+f"(d[2]), "+f"(d[3])
        : "r"(a0), "r"(a1), "r"(a2), "r"(a3), "r"(b0), "r"(b1));
}

// ---------------------------------------------------------------------------
// init
// ---------------------------------------------------------------------------
__global__ void init_kernel(const float* __restrict__ ema_w,
                            const float* __restrict__ ema_cs,
                            float* __restrict__ out) {
    int idx = blockIdx.x * blockDim.x + threadIdx.x;
    if (idx < KCB * DIM) out[O_NEW + idx] = 0.99f * ema_w[idx];
    if (idx < KCB)       out[O_NCS + idx] = 0.99f * ema_cs[idx];
    if (idx < NTOK)      g_best[idx] = 0ull;
    if (idx == 0) { g_loss = 0.0f; g_nsum = 0.0f; }
}

// ---------------------------------------------------------------------------
// wn: 0.5 * ||w_k||^2
// ---------------------------------------------------------------------------
__global__ void wn_kernel(const float* __restrict__ weight) {
    int gw = (blockIdx.x * blockDim.x + threadIdx.x) >> 5;
    int lane = threadIdx.x & 31;
    if (gw >= KCB) return;
    const float4* row = (const float4*)(weight + (size_t)gw * DIM);
    float s = 0.0f;
#pragma unroll
    for (int p = 0; p < 4; p++) {
        float4 v = row[p * 32 + lane];
        s += v.x * v.x + v.y * v.y + v.z * v.z + v.w * v.w;
    }
#pragma unroll
    for (int o = 16; o > 0; o >>= 1) s += __shfl_xor_sync(0xffffffffu, s, o);
    if (lane == 0) g_wn[gw] = 0.5f * s;
}

// ---------------------------------------------------------------------------
// split: fp32 -> 3 bf16 limbs, 6 products folded into K (row-major ext matrices)
// product p: (A-part, B-part) = 0:(h,h) 1:(h,m) 2:(m,h) 3:(m,m) 4:(h,l) 5:(l,h)
// ---------------------------------------------------------------------------
__device__ __forceinline__ void split8(const float* x, uint4& hv, uint4& mv, uint4& lv) {
    __nv_bfloat16 h[8], m[8], l[8];
#pragma unroll
    for (int i = 0; i < 8; i++) {
        float v = x[i];
        h[i] = __float2bfloat16(v);
        float r1 = v - __bfloat162float(h[i]);
        m[i] = __float2bfloat16(r1);
        float r2 = r1 - __bfloat162float(m[i]);
        l[i] = __float2bfloat16(r2);
    }
    hv = *(uint4*)h; mv = *(uint4*)m; lv = *(uint4*)l;
}

__global__ void split_z_kernel(const float* __restrict__ z) {
    int idx = blockIdx.x * blockDim.x + threadIdx.x;   // NTOK*64
    int t = idx >> 6, g = idx & 63;
    int d0 = g * 8;
    float x[8];
    *(float4*)(x)     = *(const float4*)(z + (size_t)t * DIM + d0);
    *(float4*)(x + 4) = *(const float4*)(z + (size_t)t * DIM + d0 + 4);
    uint4 hv, mv, lv;
    split8(x, hv, mv, lv);
    __nv_bfloat16* dst = g_A + (size_t)t * KEXT + d0;
    const int psel[6] = {0, 0, 1, 1, 0, 2};
#pragma unroll
    for (int pp = 0; pp < 6; pp++) {
        uint4 v = (psel[pp] == 0) ? hv : (psel[pp] == 1) ? mv : lv;
        *(uint4*)(dst + pp * DIM) = v;
    }
}

__global__ void split_w_kernel(const float* __restrict__ weight) {
    int idx = blockIdx.x * blockDim.x + threadIdx.x;   // KCB*64
    int t = idx >> 6, g = idx & 63;
    int d0 = g * 8;
    float x[8];
    *(float4*)(x)     = *(const float4*)(weight + (size_t)t * DIM + d0);
    *(float4*)(x + 4) = *(const float4*)(weight + (size_t)t * DIM + d0 + 4);
    uint4 hv, mv, lv;
    split8(x, hv, mv, lv);
    __nv_bfloat16* dst = g_B + (size_t)t * KEXT + d0;
    const int psel[6] = {0, 1, 0, 1, 2, 0};
#pragma unroll
    for (int pp = 0; pp < 6; pp++) {
        uint4 v = (psel[pp] == 0) ? hv : (psel[pp] == 1) ? mv : lv;
        *(uint4*)(dst + pp * DIM) = v;
    }
}

// ---------------------------------------------------------------------------
// pipelined bf16 mma.sync GEMM + fused argmax
// grid (KCB/BN = 64 fast, NTOK/BM = 256), 256 threads, 3-stage cp.async
// smem: A[3][128][64] | B[3][128][64] (xor-swizzled 16B chunks) | wns[128]
// ---------------------------------------------------------------------------
#define SMEM_WNS   (2 * STAGES * TILE_BYTES)           // 98304
#define SMEM_BYTES (SMEM_WNS + BN * 4)                 // 98816

__device__ __forceinline__ void load_chunk(uint32_t sb, const char* gA, const char* gB,
                                           int kc, int s, int tid) {
#pragma unroll
    for (int i = 0; i < 4; i++) {
        int idx = tid + i * 256;
        int row = idx >> 3, ch = idx & 7;
        uint32_t so = (uint32_t)(s * TILE_BYTES + row * 128 + ((ch ^ (row & 7)) << 4));
        cp16(sb + so, gA + (size_t)row * (KEXT * 2) + (size_t)kc * (BK * 2) + ch * 16);
    }
#pragma unroll
    for (int i = 0; i < 4; i++) {
        int idx = tid + i * 256;
        int row = idx >> 3, ch = idx & 7;
        uint32_t so = (uint32_t)(STAGES * TILE_BYTES + s * TILE_BYTES + row * 128 +
                                 ((ch ^ (row & 7)) << 4));
        cp16(sb + so, gB + (size_t)row * (KEXT * 2) + (size_t)kc * (BK * 2) + ch * 16);
    }
}

__global__ void __launch_bounds__(256)
argmax_mma_kernel(float* __restrict__ out) {
    extern __shared__ __align__(128) unsigned char smem[];
    const uint32_t sb = smem_u32(smem);
    const int tid = threadIdx.x;
    const int lane = tid & 31, wid = tid >> 5;
    const int wm = wid & 3, wn = wid >> 2;
    const int n_tile = blockIdx.x, m_tile = blockIdx.y;

    float* wns_s = (float*)(smem + SMEM_WNS);
    if (tid < BN) wns_s[tid] = g_wn[n_tile * BN + tid];

    const char* gA = (const char*)g_A + (size_t)m_tile * BM * (KEXT * 2);
    const char* gB = (const char*)g_B + (size_t)n_tile * BN * (KEXT * 2);

    float acc[2][8][4];
#pragma unroll
    for (int mi = 0; mi < 2; mi++)
#pragma unroll
        for (int ni = 0; ni < 8; ni++)
#pragma unroll
            for (int j = 0; j < 4; j++) acc[mi][ni][j] = 0.0f;

    // prologue: stage chunks 0..STAGES-2
#pragma unroll
    for (int i = 0; i < STAGES - 1; i++) {
        load_chunk(sb, gA, gB, i, i, tid);
        CP_COMMIT();
    }

    for (int kc = 0; kc < NCHUNK; kc++) {
        const int s = kc % STAGES;
        CP_WAIT(STAGES - 2);
        __syncthreads();
        const int pf = kc + STAGES - 1;
        if (pf < NCHUNK) load_chunk(sb, gA, gB, pf, pf % STAGES, tid);
        CP_COMMIT();

        const uint32_t aBase = sb + s * TILE_BYTES;
        const uint32_t bBase = sb + (STAGES + s) * TILE_BYTES;
#pragma unroll
        for (int ks = 0; ks < 4; ks++) {
            uint32_t a[2][4];
#pragma unroll
            for (int mi = 0; mi < 2; mi++) {
                int row = wm * 32 + mi * 16 + (lane & 15);
                int ch  = ks * 2 + (lane >> 4);
                ldsm4(a[mi][0], a[mi][1], a[mi][2], a[mi][3],
                      aBase + row * 128 + ((ch ^ (row & 7)) << 4));
            }
            uint32_t b[8][2];
#pragma unroll
            for (int p = 0; p < 4; p++) {
                int l = lane & 7, sel = lane >> 3;
                int row = wn * 64 + p * 16 + (sel & 1) * 8 + l;
                int ch  = ks * 2 + (sel >> 1);
                uint32_t r0, r1, r2, r3;
                ldsm4(r0, r1, r2, r3, bBase + row * 128 + ((ch ^ (row & 7)) << 4));
                b[2 * p][0] = r0; b[2 * p][1] = r2;
                b[2 * p + 1][0] = r1; b[2 * p + 1][1] = r3;
            }
#pragma unroll
            for (int mi = 0; mi < 2; mi++)
#pragma unroll
                for (int ni = 0; ni < 8; ni++)
                    mma16816(acc[mi][ni], a[mi][0], a[mi][1], a[mi][2], a[mi][3],
                             b[ni][0], b[ni][1]);
        }
        __syncthreads();
    }

    // epilogue: metric = acc - 0.5||w||^2, per-row argmax, quad reduce, atomicMax
#pragma unroll
    for (int mi = 0; mi < 2; mi++) {
#pragma unroll
        for (int r = 0; r < 2; r++) {
            float best = -3.4e38f;
            int bc = 0;
#pragma unroll
            for (int ni = 0; ni < 8; ni++) {
#pragma unroll
                for (int c = 0; c < 2; c++) {
                    int n = wn * 64 + ni * 8 + (lane & 3) * 2 + c;
                    float m = acc[mi][ni][r * 2 + c] - wns_s[n];
                    if (m > best) { best = m; bc = n; }
                }
            }
#pragma unroll
            for (int o = 1; o < 4; o <<= 1) {
                float bv = __shfl_xor_sync(0xffffffffu, best, o);
                int bcc  = __shfl_xor_sync(0xffffffffu, bc, o);
                if (bv > best || (bv == best && bcc < bc)) { best = bv; bc = bcc; }
            }
            if ((lane & 3) == 0) {
                int token = m_tile * BM + wm * 32 + mi * 16 + r * 8 + (lane >> 2);
                uint32_t u = __float_as_uint(best);
                uint32_t key = (u & 0x80000000u) ? ~u : (u | 0x80000000u);
                unsigned long long packed = ((unsigned long long)key << 32) |
                    (unsigned long long)(0xFFFFFFFFu - (uint32_t)(n_tile * BN + bc));
                atomicMax(&g_best[token], packed);
            }
        }
    }
}

// ---------------------------------------------------------------------------
// decode packed best -> codes
// ---------------------------------------------------------------------------
__global__ void codes_kernel(float* __restrict__ out) {
    int idx = blockIdx.x * blockDim.x + threadIdx.x;
    if (idx >= NTOK) return;
    int code = (int)(0xFFFFFFFFu - (uint32_t)(g_best[idx] & 0xFFFFFFFFull));
    g_codes[idx] = code;
    out[O_CODES + idx] = (float)code;
}

// ---------------------------------------------------------------------------
// EMA scatter / normalize / gather (validated in R1)
// ---------------------------------------------------------------------------
__global__ void scatter_kernel(const float* __restrict__ z, float* __restrict__ out) {
    int token = blockIdx.x, tid = threadIdx.x;
    int code = g_codes[token];
    if (tid == 0) atomicAdd(out + O_NCS + code, 0.01f);
    const float* zr = z + (size_t)token * DIM;
    float* dst = out + O_NEW + (size_t)code * DIM;
#pragma unroll
    for (int i = 0; i < 4; i++) {
        int d = i * 128 + tid;
        atomicAdd(dst + d, 0.01f * zr[d]);
    }
}

__global__ void nsum_kernel(const float* __restrict__ out) {
    __shared__ float red[1024];
    int tid = threadIdx.x;
    float s = 0.0f;
    for (int i = tid; i < KCB; i += 1024) s += out[O_NCS + i];
    red[tid] = s;
    __syncthreads();
    for (int o = 512; o > 0; o >>= 1) {
        if (tid < o) red[tid] += red[tid + o];
        __syncthreads();
    }
    if (tid == 0) g_nsum = red[0];
}

__global__ void weight_kernel(float* __restrict__ out) {
    int idx = blockIdx.x * blockDim.x + threadIdx.x;
    if (idx >= KCB * DIM) return;
    int k = idx >> 9;
    float n = g_nsum;
    float cs = (out[O_NCS + k] + 1e-5f) / (n + KCB * 1e-5f) * n;
    out[O_NW + idx] = out[O_NEW + idx] / cs;
}

__global__ void gather_kernel(const float* __restrict__ z, float* __restrict__ out) {
    __shared__ float red[128];
    int token = blockIdx.x, tid = threadIdx.x;
    int code = g_codes[token];
    const float* wr = out + O_NW + (size_t)code * DIM;
    const float* zr = z + (size_t)token * DIM;
    float* oq = out + O_ZQ + (size_t)token * DIM;
    float ls = 0.0f;
#pragma unroll
    for (int i = 0; i < 4; i++) {
        int d = i * 128 + tid;
        float w = wr[d], v = zr[d];
        float t = w - v;
        oq[d] = v + t;
        ls += t * t;
    }
    red[tid] = ls;
    __syncthreads();
    for (int o = 64; o > 0; o >>= 1) {
        if (tid < o) red[tid] += red[tid + o];
        __syncthreads();
    }
    if (tid == 0) atomicAdd(&g_loss, red[0]);
}

__global__ void finalize_kernel(float* __restrict__ out) {
    out[O_LOSS] = 0.25f * g_loss / (float)(NTOK * DIM);
}

// ---------------------------------------------------------------------------
extern "C" void kernel_launch(void* const* d_in, const int* in_sizes, int n_in,
                              void* d_out, int out_size) {
    const float* z      = (const float*)d_in[0];
    const float* weight = (const float*)d_in[1];
    const float* ema_cs = (const float*)d_in[2];
    const float* ema_w  = (const float*)d_in[3];
    float* out = (float*)d_out;

    cudaFuncSetAttribute(argmax_mma_kernel,
                         cudaFuncAttributeMaxDynamicSharedMemorySize, SMEM_BYTES);

    init_kernel<<<(KCB * DIM + 255) / 256, 256>>>(ema_w, ema_cs, out);
    wn_kernel<<<KCB / 8, 256>>>(weight);
    split_z_kernel<<<NTOK * 64 / 256, 256>>>(z);
    split_w_kernel<<<KCB * 64 / 256, 256>>>(weight);
    argmax_mma_kernel<<<dim3(KCB / BN, NTOK / BM), 256, SMEM_BYTES>>>(out);
    codes_kernel<<<(NTOK + 255) / 256, 256>>>(out);
    scatter_kernel<<<NTOK, 128>>>(z, out);
    nsum_kernel<<<1, 1024>>>(out);
    weight_kernel<<<(KCB * DIM + 255) / 256, 256>>>(out);
    gather_kernel<<<NTOK, 128>>>(z, out);
    finalize_kernel<<<1, 1>>>(out);
}

// round 4
// speedup vs baseline: 4.3449x; 1.4622x over previous
#include <cuda_runtime.h>
#include <cuda_bf16.h>
#include <cstdint>

#define NTOK 32768
#define DIM  512
#define KCB  8192

#define NPROD  4
#define KEXT   (NPROD * DIM)      // 2048
#define BM     128
#define BN     128
#define BK     64
#define NCHUNK (KEXT / BK)        // 32
#define STAGES 3
#define TILE_BYTES (BM * BK * 2)  // 16384

// output layout (flat float32 concat, reference return order)
#define O_LOSS  ((size_t)0)
#define O_ZQ    ((size_t)1)
#define O_CODES ((size_t)(1 + (size_t)NTOK*DIM))
#define O_NW    ((size_t)(O_CODES + NTOK))
#define O_NCS   ((size_t)(O_NW + (size_t)KCB*DIM))
#define O_NEW   ((size_t)(O_NCS + KCB))

// ---- device scratch (static: no allocation allowed) ----
__device__ __align__(16) __nv_bfloat16 g_A[(size_t)NTOK * KEXT];  // 128 MB
__device__ __align__(16) __nv_bfloat16 g_B[(size_t)KCB  * KEXT];  // 32 MB
__device__ unsigned long long g_best[NTOK];
__device__ int   g_codes[NTOK];
__device__ float g_wn[KCB];
__device__ float g_loss;
__device__ float g_nsum;

// ---------------------------------------------------------------------------
// PTX helpers (sm_80-era only: supported at base sm_103 PTX target)
// ---------------------------------------------------------------------------
__device__ __forceinline__ uint32_t smem_u32(const void* p) {
    uint32_t a;
    asm("{ .reg .u64 t; cvta.to.shared.u64 t, %1; cvt.u32.u64 %0, t; }" : "=r"(a) : "l"(p));
    return a;
}
__device__ __forceinline__ void cp16(uint32_t s, const void* g) {
    asm volatile("cp.async.cg.shared.global [%0], [%1], 16;" :: "r"(s), "l"(g));
}
#define CP_COMMIT() asm volatile("cp.async.commit_group;" ::: "memory")
#define CP_WAIT(n)  asm volatile("cp.async.wait_group %0;" :: "n"(n) : "memory")

__device__ __forceinline__ void ldsm4(uint32_t& r0, uint32_t& r1, uint32_t& r2, uint32_t& r3,
                                      uint32_t addr) {
    asm volatile("ldmatrix.sync.aligned.m8n8.x4.shared.b16 {%0,%1,%2,%3}, [%4];"
                 : "=r"(r0), "=r"(r1), "=r"(r2), "=r"(r3) : "r"(addr));
}
__device__ __forceinline__ void mma16816(float* d, uint32_t a0, uint32_t a1, uint32_t a2,
                                         uint32_t a3, uint32_t b0, uint32_t b1) {
    asm volatile(
        "mma.sync.aligned.m16n8k16.row.col.f32.bf16.bf16.f32 "
        "{%0,%1,%2,%3},{%4,%5,%6,%7},{%8,%9},{%0,%1,%2,%3};"
        : "+f"(d[0]), "+f"(d[1]), "+f"(d[2]), "+f"(d[3])
        : "r"(a0), "r"(a1), "r"(a2), "r"(a3), "r"(b0), "r"(b1));
}

// ---------------------------------------------------------------------------
// init
// ---------------------------------------------------------------------------
__global__ void init_kernel(const float* __restrict__ ema_w,
                            const float* __restrict__ ema_cs,
                            float* __restrict__ out) {
    int idx = blockIdx.x * blockDim.x + threadIdx.x;
    if (idx < KCB * DIM) out[O_NEW + idx] = 0.99f * ema_w[idx];
    if (idx < KCB)       out[O_NCS + idx] = 0.99f * ema_cs[idx];
    if (idx < NTOK)      g_best[idx] = 0ull;
    if (idx == 0) { g_loss = 0.0f; g_nsum = 0.0f; }
}

// ---------------------------------------------------------------------------
// wn: 0.5 * ||w_k||^2
// ---------------------------------------------------------------------------
__global__ void wn_kernel(const float* __restrict__ weight) {
    int gw = (blockIdx.x * blockDim.x + threadIdx.x) >> 5;
    int lane = threadIdx.x & 31;
    if (gw >= KCB) return;
    const float4* row = (const float4*)(weight + (size_t)gw * DIM);
    float s = 0.0f;
#pragma unroll
    for (int p = 0; p < 4; p++) {
        float4 v = row[p * 32 + lane];
        s += v.x * v.x + v.y * v.y + v.z * v.z + v.w * v.w;
    }
#pragma unroll
    for (int o = 16; o > 0; o >>= 1) s += __shfl_xor_sync(0xffffffffu, s, o);
    if (lane == 0) g_wn[gw] = 0.5f * s;
}

// ---------------------------------------------------------------------------
// split: fp32 -> bf16 limbs, 4 products folded into K (row-major ext matrices)
// product p: (A-part, B-part) = 0:(h,h) 1:(h,m) 2:(m,h) 3:(m,m)
// ---------------------------------------------------------------------------
__device__ __forceinline__ void split8(const float* x, uint4& hv, uint4& mv) {
    __nv_bfloat16 h[8], m[8];
#pragma unroll
    for (int i = 0; i < 8; i++) {
        float v = x[i];
        h[i] = __float2bfloat16(v);
        float r1 = v - __bfloat162float(h[i]);
        m[i] = __float2bfloat16(r1);
    }
    hv = *(uint4*)h; mv = *(uint4*)m;
}

__global__ void split_z_kernel(const float* __restrict__ z) {
    int idx = blockIdx.x * blockDim.x + threadIdx.x;   // NTOK*64
    int t = idx >> 6, g = idx & 63;
    int d0 = g * 8;
    float x[8];
    *(float4*)(x)     = *(const float4*)(z + (size_t)t * DIM + d0);
    *(float4*)(x + 4) = *(const float4*)(z + (size_t)t * DIM + d0 + 4);
    uint4 hv, mv;
    split8(x, hv, mv);
    __nv_bfloat16* dst = g_A + (size_t)t * KEXT + d0;
    // A parts per product: h, h, m, m
    *(uint4*)(dst + 0 * DIM) = hv;
    *(uint4*)(dst + 1 * DIM) = hv;
    *(uint4*)(dst + 2 * DIM) = mv;
    *(uint4*)(dst + 3 * DIM) = mv;
}

__global__ void split_w_kernel(const float* __restrict__ weight) {
    int idx = blockIdx.x * blockDim.x + threadIdx.x;   // KCB*64
    int t = idx >> 6, g = idx & 63;
    int d0 = g * 8;
    float x[8];
    *(float4*)(x)     = *(const float4*)(weight + (size_t)t * DIM + d0);
    *(float4*)(x + 4) = *(const float4*)(weight + (size_t)t * DIM + d0 + 4);
    uint4 hv, mv;
    split8(x, hv, mv);
    __nv_bfloat16* dst = g_B + (size_t)t * KEXT + d0;
    // B parts per product: h, m, h, m
    *(uint4*)(dst + 0 * DIM) = hv;
    *(uint4*)(dst + 1 * DIM) = mv;
    *(uint4*)(dst + 2 * DIM) = hv;
    *(uint4*)(dst + 3 * DIM) = mv;
}

// ---------------------------------------------------------------------------
// pipelined bf16 mma.sync GEMM + fused argmax
// grid (KCB/BN = 64 fast, NTOK/BM = 256), 256 threads, 3-stage cp.async
// smem: A[3][128][64] | B[3][128][64] (xor-swizzled 16B chunks) | wns[128]
// ---------------------------------------------------------------------------
#define SMEM_WNS   (2 * STAGES * TILE_BYTES)           // 98304
#define SMEM_BYTES (SMEM_WNS + BN * 4)                 // 98816

__device__ __forceinline__ void load_chunk(uint32_t sb, const char* gA, const char* gB,
                                           int kc, int s, int tid) {
#pragma unroll
    for (int i = 0; i < 4; i++) {
        int idx = tid + i * 256;
        int row = idx >> 3, ch = idx & 7;
        uint32_t so = (uint32_t)(s * TILE_BYTES + row * 128 + ((ch ^ (row & 7)) << 4));
        cp16(sb + so, gA + (size_t)row * (KEXT * 2) + (size_t)kc * (BK * 2) + ch * 16);
    }
#pragma unroll
    for (int i = 0; i < 4; i++) {
        int idx = tid + i * 256;
        int row = idx >> 3, ch = idx & 7;
        uint32_t so = (uint32_t)(STAGES * TILE_BYTES + s * TILE_BYTES + row * 128 +
                                 ((ch ^ (row & 7)) << 4));
        cp16(sb + so, gB + (size_t)row * (KEXT * 2) + (size_t)kc * (BK * 2) + ch * 16);
    }
}

__global__ void __launch_bounds__(256)
argmax_mma_kernel(float* __restrict__ out) {
    extern __shared__ __align__(128) unsigned char smem[];
    const uint32_t sb = smem_u32(smem);
    const int tid = threadIdx.x;
    const int lane = tid & 31, wid = tid >> 5;
    const int wm = wid & 3, wn = wid >> 2;
    const int n_tile = blockIdx.x, m_tile = blockIdx.y;

    float* wns_s = (float*)(smem + SMEM_WNS);
    if (tid < BN) wns_s[tid] = g_wn[n_tile * BN + tid];

    const char* gA = (const char*)g_A + (size_t)m_tile * BM * (KEXT * 2);
    const char* gB = (const char*)g_B + (size_t)n_tile * BN * (KEXT * 2);

    float acc[2][8][4];
#pragma unroll
    for (int mi = 0; mi < 2; mi++)
#pragma unroll
        for (int ni = 0; ni < 8; ni++)
#pragma unroll
            for (int j = 0; j < 4; j++) acc[mi][ni][j] = 0.0f;

    // prologue: stage chunks 0..STAGES-2
#pragma unroll
    for (int i = 0; i < STAGES - 1; i++) {
        load_chunk(sb, gA, gB, i, i, tid);
        CP_COMMIT();
    }

    for (int kc = 0; kc < NCHUNK; kc++) {
        const int s = kc % STAGES;
        CP_WAIT(STAGES - 2);
        __syncthreads();
        const int pf = kc + STAGES - 1;
        if (pf < NCHUNK) load_chunk(sb, gA, gB, pf, pf % STAGES, tid);
        CP_COMMIT();

        const uint32_t aBase = sb + s * TILE_BYTES;
        const uint32_t bBase = sb + (STAGES + s) * TILE_BYTES;
#pragma unroll
        for (int ks = 0; ks < 4; ks++) {
            uint32_t a[2][4];
#pragma unroll
            for (int mi = 0; mi < 2; mi++) {
                int row = wm * 32 + mi * 16 + (lane & 15);
                int ch  = ks * 2 + (lane >> 4);
                ldsm4(a[mi][0], a[mi][1], a[mi][2], a[mi][3],
                      aBase + row * 128 + ((ch ^ (row & 7)) << 4));
            }
            uint32_t b[8][2];
#pragma unroll
            for (int p = 0; p < 4; p++) {
                int l = lane & 7, sel = lane >> 3;
                int row = wn * 64 + p * 16 + (sel & 1) * 8 + l;
                int ch  = ks * 2 + (sel >> 1);
                uint32_t r0, r1, r2, r3;
                ldsm4(r0, r1, r2, r3, bBase + row * 128 + ((ch ^ (row & 7)) << 4));
                b[2 * p][0] = r0; b[2 * p][1] = r2;
                b[2 * p + 1][0] = r1; b[2 * p + 1][1] = r3;
            }
#pragma unroll
            for (int mi = 0; mi < 2; mi++)
#pragma unroll
                for (int ni = 0; ni < 8; ni++)
                    mma16816(acc[mi][ni], a[mi][0], a[mi][1], a[mi][2], a[mi][3],
                             b[ni][0], b[ni][1]);
        }
        __syncthreads();
    }

    // epilogue: metric = acc - 0.5||w||^2, per-row argmax, quad reduce, atomicMax
#pragma unroll
    for (int mi = 0; mi < 2; mi++) {
#pragma unroll
        for (int r = 0; r < 2; r++) {
            float best = -3.4e38f;
            int bc = 0;
#pragma unroll
            for (int ni = 0; ni < 8; ni++) {
#pragma unroll
                for (int c = 0; c < 2; c++) {
                    int n = wn * 64 + ni * 8 + (lane & 3) * 2 + c;
                    float m = acc[mi][ni][r * 2 + c] - wns_s[n];
                    if (m > best) { best = m; bc = n; }
                }
            }
#pragma unroll
            for (int o = 1; o < 4; o <<= 1) {
                float bv = __shfl_xor_sync(0xffffffffu, best, o);
                int bcc  = __shfl_xor_sync(0xffffffffu, bc, o);
                if (bv > best || (bv == best && bcc < bc)) { best = bv; bc = bcc; }
            }
            if ((lane & 3) == 0) {
                int token = m_tile * BM + wm * 32 + mi * 16 + r * 8 + (lane >> 2);
                uint32_t u = __float_as_uint(best);
                uint32_t key = (u & 0x80000000u) ? ~u : (u | 0x80000000u);
                unsigned long long packed = ((unsigned long long)key << 32) |
                    (unsigned long long)(0xFFFFFFFFu - (uint32_t)(n_tile * BN + bc));
                atomicMax(&g_best[token], packed);
            }
        }
    }
}

// ---------------------------------------------------------------------------
// decode packed best -> codes
// ---------------------------------------------------------------------------
__global__ void codes_kernel(float* __restrict__ out) {
    int idx = blockIdx.x * blockDim.x + threadIdx.x;
    if (idx >= NTOK) return;
    int code = (int)(0xFFFFFFFFu - (uint32_t)(g_best[idx] & 0xFFFFFFFFull));
    g_codes[idx] = code;
    out[O_CODES + idx] = (float)code;
}

// ---------------------------------------------------------------------------
// EMA scatter / normalize / gather (validated in R1/R3)
// ---------------------------------------------------------------------------
__global__ void scatter_kernel(const float* __restrict__ z, float* __restrict__ out) {
    int token = blockIdx.x, tid = threadIdx.x;
    int code = g_codes[token];
    if (tid == 0) atomicAdd(out + O_NCS + code, 0.01f);
    const float* zr = z + (size_t)token * DIM;
    float* dst = out + O_NEW + (size_t)code * DIM;
#pragma unroll
    for (int i = 0; i < 4; i++) {
        int d = i * 128 + tid;
        atomicAdd(dst + d, 0.01f * zr[d]);
    }
}

__global__ void nsum_kernel(const float* __restrict__ out) {
    __shared__ float red[1024];
    int tid = threadIdx.x;
    float s = 0.0f;
    for (int i = tid; i < KCB; i += 1024) s += out[O_NCS + i];
    red[tid] = s;
    __syncthreads();
    for (int o = 512; o > 0; o >>= 1) {
        if (tid < o) red[tid] += red[tid + o];
        __syncthreads();
    }
    if (tid == 0) g_nsum = red[0];
}

__global__ void weight_kernel(float* __restrict__ out) {
    int idx = blockIdx.x * blockDim.x + threadIdx.x;
    if (idx >= KCB * DIM) return;
    int k = idx >> 9;
    float n = g_nsum;
    float cs = (out[O_NCS + k] + 1e-5f) / (n + KCB * 1e-5f) * n;
    out[O_NW + idx] = out[O_NEW + idx] / cs;
}

__global__ void gather_kernel(const float* __restrict__ z, float* __restrict__ out) {
    __shared__ float red[128];
    int token = blockIdx.x, tid = threadIdx.x;
    int code = g_codes[token];
    const float* wr = out + O_NW + (size_t)code * DIM;
    const float* zr = z + (size_t)token * DIM;
    float* oq = out + O_ZQ + (size_t)token * DIM;
    float ls = 0.0f;
#pragma unroll
    for (int i = 0; i < 4; i++) {
        int d = i * 128 + tid;
        float w = wr[d], v = zr[d];
        float t = w - v;
        oq[d] = v + t;
        ls += t * t;
    }
    red[tid] = ls;
    __syncthreads();
    for (int o = 64; o > 0; o >>= 1) {
        if (tid < o) red[tid] += red[tid + o];
        __syncthreads();
    }
    if (tid == 0) atomicAdd(&g_loss, red[0]);
}

__global__ void finalize_kernel(float* __restrict__ out) {
    out[O_LOSS] = 0.25f * g_loss / (float)(NTOK * DIM);
}

// ---------------------------------------------------------------------------
extern "C" void kernel_launch(void* const* d_in, const int* in_sizes, int n_in,
                              void* d_out, int out_size) {
    const float* z      = (const float*)d_in[0];
    const float* weight = (const float*)d_in[1];
    const float* ema_cs = (const float*)d_in[2];
    const float* ema_w  = (const float*)d_in[3];
    float* out = (float*)d_out;

    cudaFuncSetAttribute(argmax_mma_kernel,
                         cudaFuncAttributeMaxDynamicSharedMemorySize, SMEM_BYTES);

    init_kernel<<<(KCB * DIM + 255) / 256, 256>>>(ema_w, ema_cs, out);
    wn_kernel<<<KCB / 8, 256>>>(weight);
    split_z_kernel<<<NTOK * 64 / 256, 256>>>(z);
    split_w_kernel<<<KCB * 64 / 256, 256>>>(weight);
    argmax_mma_kernel<<<dim3(KCB / BN, NTOK / BM), 256, SMEM_BYTES>>>(out);
    codes_kernel<<<(NTOK + 255) / 256, 256>>>(out);
    scatter_kernel<<<NTOK, 128>>>(z, out);
    nsum_kernel<<<1, 1024>>>(out);
    weight_kernel<<<(KCB * DIM + 255) / 256, 256>>>(out);
    gather_kernel<<<NTOK, 128>>>(z, out);
    finalize_kernel<<<1, 1>>>(out);
}

// round 5
// speedup vs baseline: 9.8787x; 2.2736x over previous
#include <cuda_runtime.h>
#include <cuda_bf16.h>
#include <cstdint>

#define NTOK 32768
#define DIM  512
#define KCB  8192

#define BM     128
#define BN     128
#define BK     64
#define NCHUNK (DIM / BK)         // 8
#define STAGES 3
#define TILE_BYTES (BM * BK * 2)  // 16384

// output layout (flat float32 concat, reference return order)
#define O_LOSS  ((size_t)0)
#define O_ZQ    ((size_t)1)
#define O_CODES ((size_t)(1 + (size_t)NTOK*DIM))
#define O_NW    ((size_t)(O_CODES + NTOK))
#define O_NCS   ((size_t)(O_NW + (size_t)KCB*DIM))
#define O_NEW   ((size_t)(O_NCS + KCB))

// ---- device scratch (static: no allocation allowed) ----
__device__ __align__(16) __nv_bfloat16 g_A[(size_t)NTOK * DIM];   // 32 MB
__device__ __align__(16) __nv_bfloat16 g_B[(size_t)KCB  * DIM];   // 8 MB
__device__ __align__(16) float g_metric[(size_t)NTOK * KCB];      // 1 GB coarse metrics
__device__ int   g_codes[NTOK];
__device__ float g_wn[KCB];
__device__ float g_loss;
__device__ float g_nsum;

// ---------------------------------------------------------------------------
// PTX helpers (sm_80-era only: supported at base sm_103 PTX target)
// ---------------------------------------------------------------------------
__device__ __forceinline__ uint32_t smem_u32(const void* p) {
    uint32_t a;
    asm("{ .reg .u64 t; cvta.to.shared.u64 t, %1; cvt.u32.u64 %0, t; }" : "=r"(a) : "l"(p));
    return a;
}
__device__ __forceinline__ void cp16(uint32_t s, const void* g) {
    asm volatile("cp.async.cg.shared.global [%0], [%1], 16;" :: "r"(s), "l"(g));
}
#define CP_COMMIT() asm volatile("cp.async.commit_group;" ::: "memory")
#define CP_WAIT(n)  asm volatile("cp.async.wait_group %0;" :: "n"(n) : "memory")

__device__ __forceinline__ void ldsm4(uint32_t& r0, uint32_t& r1, uint32_t& r2, uint32_t& r3,
                                      uint32_t addr) {
    asm volatile("ldmatrix.sync.aligned.m8n8.x4.shared.b16 {%0,%1,%2,%3}, [%4];"
                 : "=r"(r0), "=r"(r1), "=r"(r2), "=r"(r3) : "r"(addr));
}
__device__ __forceinline__ void mma16816(float* d, uint32_t a0, uint32_t a1, uint32_t a2,
                                         uint32_t a3, uint32_t b0, uint32_t b1) {
    asm volatile(
        "mma.sync.aligned.m16n8k16.row.col.f32.bf16.bf16.f32 "
        "{%0,%1,%2,%3},{%4,%5,%6,%7},{%8,%9},{%0,%1,%2,%3};"
        : "+f"(d[0]), "+f"(d[1]), "+f"(d[2]), "+f"(d[3])
        : "r"(a0), "r"(a1), "r"(a2), "r"(a3), "r"(b0), "r"(b1));
}

// ---------------------------------------------------------------------------
// init
// ---------------------------------------------------------------------------
__global__ void init_kernel(const float* __restrict__ ema_w,
                            const float* __restrict__ ema_cs,
                            float* __restrict__ out) {
    int idx = blockIdx.x * blockDim.x + threadIdx.x;
    if (idx < KCB * DIM) out[O_NEW + idx] = 0.99f * ema_w[idx];
    if (idx < KCB)       out[O_NCS + idx] = 0.99f * ema_cs[idx];
    if (idx == 0) { g_loss = 0.0f; g_nsum = 0.0f; }
}

// ---------------------------------------------------------------------------
// wn: 0.5 * ||w_k||^2 (exact fp32)
// ---------------------------------------------------------------------------
__global__ void wn_kernel(const float* __restrict__ weight) {
    int gw = (blockIdx.x * blockDim.x + threadIdx.x) >> 5;
    int lane = threadIdx.x & 31;
    if (gw >= KCB) return;
    const float4* row = (const float4*)(weight + (size_t)gw * DIM);
    float s = 0.0f;
#pragma unroll
    for (int p = 0; p < 4; p++) {
        float4 v = row[p * 32 + lane];
        s += v.x * v.x + v.y * v.y + v.z * v.z + v.w * v.w;
    }
#pragma unroll
    for (int o = 16; o > 0; o >>= 1) s += __shfl_xor_sync(0xffffffffu, s, o);
    if (lane == 0) g_wn[gw] = 0.5f * s;
}

// ---------------------------------------------------------------------------
// convert fp32 -> bf16 (coarse operands)
// ---------------------------------------------------------------------------
__global__ void conv_kernel(const float* __restrict__ src, __nv_bfloat16* __restrict__ dst,
                            int n8) {
    int idx = blockIdx.x * blockDim.x + threadIdx.x;
    if (idx >= n8) return;
    const float4* s4 = (const float4*)src + (size_t)idx * 2;
    float4 a = s4[0], b = s4[1];
    __nv_bfloat16 h[8] = {
        __float2bfloat16(a.x), __float2bfloat16(a.y), __float2bfloat16(a.z), __float2bfloat16(a.w),
        __float2bfloat16(b.x), __float2bfloat16(b.y), __float2bfloat16(b.z), __float2bfloat16(b.w)};
    *(uint4*)(dst + (size_t)idx * 8) = *(uint4*)h;
}

// ---------------------------------------------------------------------------
// coarse bf16 GEMM: metric[t][k] = dot_bf16(z_t, w_k) - 0.5||w_k||^2 -> g_metric
// grid (KCB/BN = 64 fast, NTOK/BM = 256), 256 threads, 3-stage cp.async
// ---------------------------------------------------------------------------
#define SMEM_WNS   (2 * STAGES * TILE_BYTES)           // 98304
#define SMEM_BYTES (SMEM_WNS + BN * 4)                 // 98816

__device__ __forceinline__ void load_chunk(uint32_t sb, const char* gA, const char* gB,
                                           int kc, int s, int tid) {
#pragma unroll
    for (int i = 0; i < 4; i++) {
        int idx = tid + i * 256;
        int row = idx >> 3, ch = idx & 7;
        uint32_t so = (uint32_t)(s * TILE_BYTES + row * 128 + ((ch ^ (row & 7)) << 4));
        cp16(sb + so, gA + (size_t)row * (DIM * 2) + (size_t)kc * (BK * 2) + ch * 16);
    }
#pragma unroll
    for (int i = 0; i < 4; i++) {
        int idx = tid + i * 256;
        int row = idx >> 3, ch = idx & 7;
        uint32_t so = (uint32_t)(STAGES * TILE_BYTES + s * TILE_BYTES + row * 128 +
                                 ((ch ^ (row & 7)) << 4));
        cp16(sb + so, gB + (size_t)row * (DIM * 2) + (size_t)kc * (BK * 2) + ch * 16);
    }
}

__global__ void __launch_bounds__(256)
coarse_mma_kernel() {
    extern __shared__ __align__(128) unsigned char smem[];
    const uint32_t sb = smem_u32(smem);
    const int tid = threadIdx.x;
    const int lane = tid & 31, wid = tid >> 5;
    const int wm = wid & 3, wn = wid >> 2;
    const int n_tile = blockIdx.x, m_tile = blockIdx.y;

    float* wns_s = (float*)(smem + SMEM_WNS);
    if (tid < BN) wns_s[tid] = g_wn[n_tile * BN + tid];

    const char* gA = (const char*)g_A + (size_t)m_tile * BM * (DIM * 2);
    const char* gB = (const char*)g_B + (size_t)n_tile * BN * (DIM * 2);

    float acc[2][8][4];
#pragma unroll
    for (int mi = 0; mi < 2; mi++)
#pragma unroll
        for (int ni = 0; ni < 8; ni++)
#pragma unroll
            for (int j = 0; j < 4; j++) acc[mi][ni][j] = 0.0f;

#pragma unroll
    for (int i = 0; i < STAGES - 1; i++) {
        load_chunk(sb, gA, gB, i, i, tid);
        CP_COMMIT();
    }

    for (int kc = 0; kc < NCHUNK; kc++) {
        const int s = kc % STAGES;
        CP_WAIT(STAGES - 2);
        __syncthreads();
        const int pf = kc + STAGES - 1;
        if (pf < NCHUNK) load_chunk(sb, gA, gB, pf, pf % STAGES, tid);
        CP_COMMIT();

        const uint32_t aBase = sb + s * TILE_BYTES;
        const uint32_t bBase = sb + (STAGES + s) * TILE_BYTES;
#pragma unroll
        for (int ks = 0; ks < 4; ks++) {
            uint32_t a[2][4];
#pragma unroll
            for (int mi = 0; mi < 2; mi++) {
                int row = wm * 32 + mi * 16 + (lane & 15);
                int ch  = ks * 2 + (lane >> 4);
                ldsm4(a[mi][0], a[mi][1], a[mi][2], a[mi][3],
                      aBase + row * 128 + ((ch ^ (row & 7)) << 4));
            }
            uint32_t b[8][2];
#pragma unroll
            for (int p = 0; p < 4; p++) {
                int l = lane & 7, sel = lane >> 3;
                int row = wn * 64 + p * 16 + (sel & 1) * 8 + l;
                int ch  = ks * 2 + (sel >> 1);
                uint32_t r0, r1, r2, r3;
                ldsm4(r0, r1, r2, r3, bBase + row * 128 + ((ch ^ (row & 7)) << 4));
                b[2 * p][0] = r0; b[2 * p][1] = r2;
                b[2 * p + 1][0] = r1; b[2 * p + 1][1] = r3;
            }
#pragma unroll
            for (int mi = 0; mi < 2; mi++)
#pragma unroll
                for (int ni = 0; ni < 8; ni++)
                    mma16816(acc[mi][ni], a[mi][0], a[mi][1], a[mi][2], a[mi][3],
                             b[ni][0], b[ni][1]);
        }
        __syncthreads();
    }

    // epilogue: store coarse metric tile (float2, 8B-aligned)
#pragma unroll
    for (int mi = 0; mi < 2; mi++) {
#pragma unroll
        for (int r = 0; r < 2; r++) {
            int token = m_tile * BM + wm * 32 + mi * 16 + r * 8 + (lane >> 2);
            float* rowp = g_metric + (size_t)token * KCB + n_tile * BN;
#pragma unroll
            for (int ni = 0; ni < 8; ni++) {
                int n0 = wn * 64 + ni * 8 + (lane & 3) * 2;
                float2 v;
                v.x = acc[mi][ni][r * 2 + 0] - wns_s[n0];
                v.y = acc[mi][ni][r * 2 + 1] - wns_s[n0 + 1];
                *(float2*)(rowp + n0) = v;
            }
        }
    }
}

// ---------------------------------------------------------------------------
// scan + exact refine: per token, candidates within T of coarse max get an
// exact fp32 metric; best (tie -> lowest index) becomes the code.
// ---------------------------------------------------------------------------
#define CAND_MAX 256
#define THRESH   0.75f

__global__ void __launch_bounds__(256)
scan_refine_kernel(const float* __restrict__ z, const float* __restrict__ weight,
                   float* __restrict__ out) {
    __shared__ float met[KCB];          // 32 KB
    __shared__ float red[256];
    __shared__ int   cand[CAND_MAX];
    __shared__ int   ccount;
    __shared__ float s_best;
    __shared__ int   s_bidx;

    const int token = blockIdx.x;
    const int tid = threadIdx.x;

    // load coarse metric row, track local max
    const float4* src = (const float4*)(g_metric + (size_t)token * KCB);
    float lmax = -3.4e38f;
#pragma unroll
    for (int i = 0; i < 8; i++) {
        float4 v = src[tid + i * 256];
        ((float4*)met)[tid + i * 256] = v;
        lmax = fmaxf(lmax, fmaxf(fmaxf(v.x, v.y), fmaxf(v.z, v.w)));
    }
    red[tid] = lmax;
    if (tid == 0) ccount = 0;
    __syncthreads();
#pragma unroll
    for (int o = 128; o > 0; o >>= 1) {
        if (tid < o) red[tid] = fmaxf(red[tid], red[tid + o]);
        __syncthreads();
    }
    const float thresh = red[0] - THRESH;
    __syncthreads();

    // collect candidates
    for (int i = tid; i < KCB; i += 256) {
        if (met[i] >= thresh) {
            int p = atomicAdd(&ccount, 1);
            if (p < CAND_MAX) cand[p] = i;
        }
    }
    __syncthreads();
    int nc = ccount;
    if (nc > CAND_MAX) nc = CAND_MAX;

    // exact refine each candidate with a block-wide fp32 dot
    const float2* zr = (const float2*)(z + (size_t)token * DIM);
    float2 zv = zr[tid];   // DIM=512 -> 256 float2, one per thread
    if (tid == 0) { s_best = -3.4e38f; s_bidx = 0; }
    __syncthreads();
    for (int c = 0; c < nc; c++) {
        int k = cand[c];
        const float2* wr = (const float2*)(weight + (size_t)k * DIM);
        float2 wv = wr[tid];
        red[tid] = zv.x * wv.x + zv.y * wv.y;
        __syncthreads();
#pragma unroll
        for (int o = 128; o > 0; o >>= 1) {
            if (tid < o) red[tid] += red[tid + o];
            __syncthreads();
        }
        if (tid == 0) {
            float m = red[0] - g_wn[k];
            if (m > s_best || (m == s_best && k < s_bidx)) { s_best = m; s_bidx = k; }
        }
        __syncthreads();
    }
    if (tid == 0) {
        g_codes[token] = s_bidx;
        out[O_CODES + token] = (float)s_bidx;
    }
}

// ---------------------------------------------------------------------------
// EMA scatter / normalize / gather (validated in R1/R3/R4)
// ---------------------------------------------------------------------------
__global__ void scatter_kernel(const float* __restrict__ z, float* __restrict__ out) {
    int token = blockIdx.x, tid = threadIdx.x;
    int code = g_codes[token];
    if (tid == 0) atomicAdd(out + O_NCS + code, 0.01f);
    const float* zr = z + (size_t)token * DIM;
    float* dst = out + O_NEW + (size_t)code * DIM;
#pragma unroll
    for (int i = 0; i < 4; i++) {
        int d = i * 128 + tid;
        atomicAdd(dst + d, 0.01f * zr[d]);
    }
}

__global__ void nsum_kernel(const float* __restrict__ out) {
    __shared__ float red[1024];
    int tid = threadIdx.x;
    float s = 0.0f;
    for (int i = tid; i < KCB; i += 1024) s += out[O_NCS + i];
    red[tid] = s;
    __syncthreads();
    for (int o = 512; o > 0; o >>= 1) {
        if (tid < o) red[tid] += red[tid + o];
        __syncthreads();
    }
    if (tid == 0) g_nsum = red[0];
}

__global__ void weight_kernel(float* __restrict__ out) {
    int idx = blockIdx.x * blockDim.x + threadIdx.x;
    if (idx >= KCB * DIM) return;
    int k = idx >> 9;
    float n = g_nsum;
    float cs = (out[O_NCS + k] + 1e-5f) / (n + KCB * 1e-5f) * n;
    out[O_NW + idx] = out[O_NEW + idx] / cs;
}

__global__ void gather_kernel(const float* __restrict__ z, float* __restrict__ out) {
    __shared__ float red[128];
    int token = blockIdx.x, tid = threadIdx.x;
    int code = g_codes[token];
    const float* wr = out + O_NW + (size_t)code * DIM;
    const float* zr = z + (size_t)token * DIM;
    float* oq = out + O_ZQ + (size_t)token * DIM;
    float ls = 0.0f;
#pragma unroll
    for (int i = 0; i < 4; i++) {
        int d = i * 128 + tid;
        float w = wr[d], v = zr[d];
        float t = w - v;
        oq[d] = v + t;
        ls += t * t;
    }
    red[tid] = ls;
    __syncthreads();
    for (int o = 64; o > 0; o >>= 1) {
        if (tid < o) red[tid] += red[tid + o];
        __syncthreads();
    }
    if (tid == 0) atomicAdd(&g_loss, red[0]);
}

__global__ void finalize_kernel(float* __restrict__ out) {
    out[O_LOSS] = 0.25f * g_loss / (float)(NTOK * DIM);
}

// ---------------------------------------------------------------------------
extern "C" void kernel_launch(void* const* d_in, const int* in_sizes, int n_in,
                              void* d_out, int out_size) {
    const float* z      = (const float*)d_in[0];
    const float* weight = (const float*)d_in[1];
    const float* ema_cs = (const float*)d_in[2];
    const float* ema_w  = (const float*)d_in[3];
    float* out = (float*)d_out;

    cudaFuncSetAttribute(coarse_mma_kernel,
                         cudaFuncAttributeMaxDynamicSharedMemorySize, SMEM_BYTES);

    init_kernel<<<(KCB * DIM + 255) / 256, 256>>>(ema_w, ema_cs, out);
    wn_kernel<<<KCB / 8, 256>>>(weight);
    {
        __nv_bfloat16* dA = nullptr; cudaGetSymbolAddress((void**)&dA, g_A);
        __nv_bfloat16* dB = nullptr; cudaGetSymbolAddress((void**)&dB, g_B);
        conv_kernel<<<(NTOK * DIM / 8 + 255) / 256, 256>>>(z, dA, NTOK * DIM / 8);
        conv_kernel<<<(KCB * DIM / 8 + 255) / 256, 256>>>(weight, dB, KCB * DIM / 8);
    }
    coarse_mma_kernel<<<dim3(KCB / BN, NTOK / BM), 256, SMEM_BYTES>>>();
    scan_refine_kernel<<<NTOK, 256>>>(z, weight, out);
    scatter_kernel<<<NTOK, 128>>>(z, out);
    nsum_kernel<<<1, 1024>>>(out);
    weight_kernel<<<(KCB * DIM + 255) / 256, 256>>>(out);
    gather_kernel<<<NTOK, 128>>>(z, out);
    finalize_kernel<<<1, 1>>>(out);
}